// round 1
// baseline (speedup 1.0000x reference)
#include <cuda_runtime.h>
#include <cuda_bf16.h>
#include <math.h>

// Problem constants (fixed by the reference setup)
#define NSAMP 64
#define TLEN  512
#define DDIM  16
#define BIGV  1e10f
#define NDIAG 1023              // kk = 0..1022  (k = kk+2 in reference indexing)

// Scratch: D in diagonal-major layout: g_Ddiag[n][kk][ii], kk padded stride 1024 rows of 512
__device__ float g_Ddiag[(size_t)NSAMP * 1024 * 512];   // 134 MB
__device__ float g_res[NSAMP];

// ---------------------------------------------------------------------------
// Kernel A: compute D[n,ii,jj] = ||X[n,ii]-Z[jj]||^2 and store DIAGONAL-major.
// grid = (8 row-tiles, 64 samples), 512 threads. Tile = 64 rows x 512 cols.
// Shared tile stride 514 (even) => diagonal reads stride 513 (odd) => conflict-free.
// ---------------------------------------------------------------------------
__global__ void __launch_bounds__(512) compute_D_kernel(const float* __restrict__ X,
                                                        const float* __restrict__ Z)
{
    extern __shared__ float sm[];
    float* ts  = sm;                         // 64*514 floats
    float* zsh = ts  + 64 * 514;             // 512*17 floats (pad 17: conflict-free)
    float* z2s = zsh + 512 * 17;             // 512
    float* xs  = z2s + 512;                  // 64*16

    const int n    = blockIdx.y;
    const int row0 = blockIdx.x * 64;
    const int tid  = threadIdx.x;
    const int w    = tid >> 5;
    const int lane = tid & 31;

    // Stage Z (coalesced read, padded-stride smem)
    for (int i = tid; i < 512 * 16; i += 512)
        zsh[(i >> 4) * 17 + (i & 15)] = Z[i];
    // Stage X tile (coalesced)
    const float* Xn = X + ((size_t)n * TLEN + row0) * DDIM;
    for (int i = tid; i < 64 * 16; i += 512)
        xs[i] = Xn[i];
    __syncthreads();

    // z2 per Z row
    {
        float s = 0.f;
        #pragma unroll
        for (int c = 0; c < 16; c++) { float v = zsh[tid * 17 + c]; s = fmaf(v, v, s); }
        z2s[tid] = s;
    }

    // Each warp owns 4 consecutive rows of the tile; X rows -> registers
    float xr[4][16], x2r[4];
    #pragma unroll
    for (int q = 0; q < 4; q++) {
        float s = 0.f;
        #pragma unroll
        for (int c = 0; c < 16; c++) {
            float v = xs[(w * 4 + q) * 16 + c];
            xr[q][c] = v; s = fmaf(v, v, s);
        }
        x2r[q] = s;
    }
    __syncthreads();   // z2s ready

    // Compute tile into shared (row-major in smem, stride 514)
    #pragma unroll 1
    for (int t = 0; t < 16; t++) {
        const int jj = lane + 32 * t;
        float zr[16];
        #pragma unroll
        for (int c = 0; c < 16; c++) zr[c] = zsh[jj * 17 + c];   // stride-17: conflict-free
        const float z2v = z2s[jj];
        #pragma unroll
        for (int q = 0; q < 4; q++) {
            float acc = 0.f;
            #pragma unroll
            for (int c = 0; c < 16; c++) acc = fmaf(xr[q][c], zr[c], acc);
            const float dv = fmaf(acc, -2.0f, x2r[q] + z2v);
            ts[(w * 4 + q) * 514 + jj] = dv;                     // lanes contiguous: no conflict
        }
    }
    __syncthreads();

    // Write-out: diagonal-major, contiguous global segments.
    // Diagonals touching this tile: kk in [row0, row0+574]
    const size_t base = (size_t)n * (1024 * 512);
    for (int kkoff = w; kkoff < 575; kkoff += 16) {
        const int kk   = row0 + kkoff;                 // <= 448+574 = 1022
        const int iilo = max(row0, kk - 511);
        const int iihi = min(row0 + 63, kk);
        for (int ii = iilo + lane; ii <= iihi; ii += 32) {
            // smem read stride (ii varies): 514-1 = 513 (odd) -> conflict-free
            g_Ddiag[base + (size_t)kk * 512 + ii] = ts[(ii - row0) * 514 + (kk - ii)];
        }
    }
}

// ---------------------------------------------------------------------------
// Kernel B: soft-DTW wavefront DP. 64 blocks (1/sample), 512 threads (1/row).
// R diagonals in registers; r_up via shfl_up; warp boundaries via ping-pong smem.
// D prefetched 4 diagonals deep (covers DRAM latency).
// ---------------------------------------------------------------------------
__global__ void __launch_bounds__(512) dp_kernel()
{
    const int n    = blockIdx.x;
    const int tid  = threadIdx.x;
    const int w    = tid >> 5;
    const int lane = tid & 31;

    __shared__ float sb[2][20];              // [parity][warp] boundary values
    if (tid < 40) (&sb[0][0])[tid] = BIGV;

    float r_cur  = BIGV;                     // R on diag k-1 at this row
    float r_diag = (tid == 0) ? 0.0f : BIGV; // R[i-1][j-1] for the upcoming step

    const float* __restrict__ Dn = g_Ddiag + (size_t)n * (1024 * 512);
    float dbuf[4];
    #pragma unroll
    for (int i = 0; i < 4; i++) dbuf[i] = Dn[(size_t)i * 512 + tid];

    __syncthreads();

    #pragma unroll 4
    for (int kk = 0; kk < NDIAG; ++kk) {
        float up = __shfl_up_sync(0xffffffffu, r_cur, 1);
        if (lane == 0) up = (w == 0) ? BIGV : sb[kk & 1][w - 1];
        const float left = r_cur;
        const float dia  = r_diag;

        // softmin (gamma=1): one exp term is exactly 1 -> only 2 EX2 + 1 LG2
        const float m   = fminf(fminf(up, left), dia);
        const float Mx  = fmaxf(fmaxf(up, left), dia);
        const float mid = ((up + left) + dia) - m - Mx;
        const float s   = 1.0f + __expf(m - mid) + __expf(m - Mx);
        float newv = dbuf[kk & 3] + (m - __logf(s));

        const int jj = kk - tid;                       // column index j-1
        if ((unsigned)jj >= 512u) newv = BIGV;         // outside the DP band

        r_diag = up;
        r_cur  = newv;
        if (lane == 31) sb[(kk + 1) & 1][w] = newv;    // for next warp, next step

        if (kk + 4 < NDIAG) dbuf[kk & 3] = Dn[(size_t)(kk + 4) * 512 + tid];
        __syncthreads();
    }

    if (tid == TLEN - 1) g_res[n] = r_cur;             // R[T,T]
}

// ---------------------------------------------------------------------------
// Kernel C: deterministic weighted reduction (fixed-order tree).
// ---------------------------------------------------------------------------
__global__ void reduce_kernel(const float* __restrict__ wts, float* __restrict__ out)
{
    __shared__ float s[64];
    const int tid = threadIdx.x;
    s[tid] = g_res[tid] * wts[tid];
    __syncthreads();
    #pragma unroll
    for (int off = 32; off > 0; off >>= 1) {
        if (tid < off) s[tid] += s[tid + off];
        __syncthreads();
    }
    if (tid == 0) out[0] = s[0];
}

// ---------------------------------------------------------------------------
extern "C" void kernel_launch(void* const* d_in, const int* in_sizes, int n_in,
                              void* d_out, int out_size)
{
    // Identify inputs by element count (X: 524288, weights: 64, Z: 8192)
    const float* X = nullptr; const float* wts = nullptr; const float* Z = nullptr;
    for (int i = 0; i < n_in; i++) {
        if      (in_sizes[i] == NSAMP)        wts = (const float*)d_in[i];
        else if (in_sizes[i] == TLEN * DDIM)  Z   = (const float*)d_in[i];
        else                                  X   = (const float*)d_in[i];
    }
    float* out = (float*)d_out;

    const int smemA = (64 * 514 + 512 * 17 + 512 + 64 * 16) * (int)sizeof(float); // 172544 B
    cudaFuncSetAttribute(compute_D_kernel, cudaFuncAttributeMaxDynamicSharedMemorySize, smemA);

    compute_D_kernel<<<dim3(8, NSAMP), 512, smemA>>>(X, Z);
    dp_kernel<<<NSAMP, 512>>>();
    reduce_kernel<<<1, 64>>>(wts, out);
}